// round 15
// baseline (speedup 1.0000x reference)
#include <cuda_runtime.h>
#include <cuda_bf16.h>

// Problem dims (maxima; runtime B derived from in_sizes)
#define B_   16384
#define N_   20
#define D_   128
#define H_   4
#define DM_  384
#define DK_  96

// ---------------- scratch (device globals: no allocation allowed) ----------
__device__ float g_qin2[(size_t)B_ * 256];       // [src | src_t]      (B,256) compact q_in
__device__ float g_q  [(size_t)B_ * DM_];        // q = qin @ Wq^T     (B,384)
__device__ float g_p  [(size_t)B_ * H_ * DM_];   // p[b,h,:] = q_h @ Wk_h  (B,1536)
__device__ float g_u  [(size_t)B_ * H_ * DM_];   // u[b,h,:] = sum_n attn*k_in (B,1536)
__device__ float g_o0 [(size_t)B_ * DM_];        // attn output proj   (B,384)
__device__ float g_fc [(size_t)B_ * DM_];        // fc(out0)+fc_b      (B,384)
__device__ float g_x  [(size_t)B_ * 512];        // [LN(out) | src]    (B,512)
__device__ float g_hh [(size_t)B_ * D_];         // relu(m1)           (B,128)
__device__ int   g_maskmode;                     // 0=u8 1=i32 2=f32 3=bf16

// ---------------- mask dtype detection ------------------------------------
__global__ void detect_mask_kernel(const unsigned int* __restrict__ m, int nwords) {
    __shared__ int fBf, fF, fByte;
    int tid = threadIdx.x;
    if (tid == 0) { fBf = 0; fF = 0; fByte = 0; }
    __syncthreads();
    int lBf = 0, lF = 0, lB = 0;
    for (int i = tid; i < nwords; i += 256) {
        unsigned w = m[i];
        if (w == 0x3F803F80u || w == 0x00003F80u) lBf = 1;
        else if (w == 0x3F800000u)                lF = 1;
        else if (w > 1u)                          lB = 1;
    }
    if (lBf) atomicOr(&fBf, 1);
    if (lF)  atomicOr(&fF, 1);
    if (lB)  atomicOr(&fByte, 1);
    __syncthreads();
    if (tid == 0) g_maskmode = fBf ? 3 : (fF ? 2 : (fByte ? 0 : 1));
}

__device__ __forceinline__ bool mask_at(const void* m, int mode, size_t idx) {
    if (mode == 0) return ((const unsigned char*)m)[idx] != 0;
    if (mode == 1) return ((const int*)m)[idx] != 0;
    if (mode == 2) return ((const float*)m)[idx] != 0.0f;
    return __bfloat162float(((const __nv_bfloat16*)m)[idx]) != 0.0f;
}

// ---------------- time encoding + compact q_in build -----------------------
__global__ __launch_bounds__(128) void timeq_kernel(
    const float* __restrict__ src, const float* __restrict__ src_ts,
    const float* __restrict__ freq, const float* __restrict__ phase)
{
    int b = blockIdx.x, d = threadIdx.x;
    float t  = src_ts[b];
    float sv = src[(size_t)b * D_ + d];
    float ct = cosf(t * freq[d] + phase[d]);
    size_t base2 = (size_t)b * 256;
    g_qin2[base2 + d]       = sv;
    g_qin2[base2 + 128 + d] = ct;
}

// ---------------- generic fp32 SGEMM  C = A @ B (+bias)(+relu) -------------
// Software-pipelined: next tile's global loads are issued into registers
// before computing the current smem tile, hiding LDG latency behind FMAs.
// WT=true : Bmat[k][n] = W[n*ldw + wcol(k)]  (C = A @ W^T, W is (Nout,Kw) row-major)
// WT=false: Bmat[k][n] = W[k*ldw + n]        (C = A @ W,   W is (K,Nout) row-major)
// wskip: if >0, logical k >= wskip maps to W column k + wskip (skips a zero
//        block of width wskip in W's K dimension). Must be a multiple of BK.
// blockIdx.z applies per-z pointer offsets (azs/wzs/czs) for batched-by-head use.
// M rows beyond the runtime M are guarded on the A-load/store side by the
// grid sizing (grid.y = ceil(M/BM)) plus the m < M store predicate.
#define BM 128
#define BN 128
#define BK 8

template <bool WT>
__global__ __launch_bounds__(256, 2) void sgemm_kernel(
    const float* __restrict__ A, int lda, int azs,
    const float* __restrict__ W, int ldw, int wzs,
    float* __restrict__ C, int ldc, int czs,
    int M, int Nout, int K,
    const float* __restrict__ bias, int relu, int wskip)
{
    A += (size_t)blockIdx.z * azs;
    W += (size_t)blockIdx.z * wzs;
    C += (size_t)blockIdx.z * czs;

    __shared__ float As[BK][BM];
    __shared__ float Bs[BK][BN];

    const int tid = threadIdx.x;
    const int m0 = blockIdx.y * BM;
    const int n0 = blockIdx.x * BN;
    const int tr = tid >> 4;          // 0..15  (8 rows each)
    const int tc = tid & 15;          // 0..15  (8 cols each)

    // A tile load mapping: 128 rows x 8 k, float4 per thread
    const int arow = tid >> 1;
    const int akc  = (tid & 1) * 4;
    // W tile (modeN): 8 k-rows x 128 n, float4 per thread
    const int nkr = tid >> 5;
    const int nnc = (tid & 31) * 4;

    auto loadA = [&](int k0) -> float4 {
        int m = m0 + arow;
        if (m < M)
            return *(const float4*)&A[(size_t)m * lda + k0 + akc];
        return make_float4(0.f, 0.f, 0.f, 0.f);
    };
    auto loadW = [&](int k0) -> float4 {
        if (WT) {
            int kphys = k0 + akc;
            if (wskip && kphys >= wskip) kphys += wskip;
            if (n0 + arow < Nout)
                return *(const float4*)&W[(size_t)(n0 + arow) * ldw + kphys];
            return make_float4(0.f, 0.f, 0.f, 0.f);
        } else {
            if (n0 + nnc < Nout)
                return *(const float4*)&W[(size_t)(k0 + nkr) * ldw + n0 + nnc];
            return make_float4(0.f, 0.f, 0.f, 0.f);
        }
    };
    auto commit = [&](float4 av, float4 wv) {
        As[akc + 0][arow] = av.x; As[akc + 1][arow] = av.y;
        As[akc + 2][arow] = av.z; As[akc + 3][arow] = av.w;
        if (WT) {
            Bs[akc + 0][arow] = wv.x; Bs[akc + 1][arow] = wv.y;
            Bs[akc + 2][arow] = wv.z; Bs[akc + 3][arow] = wv.w;
        } else {
            *(float4*)&Bs[nkr][nnc] = wv;
        }
    };

    float acc[8][8];
#pragma unroll
    for (int i = 0; i < 8; i++)
#pragma unroll
        for (int j = 0; j < 8; j++) acc[i][j] = 0.0f;

    auto computeTile = [&]() {
#pragma unroll
        for (int kk = 0; kk < BK; kk++) {
            float a[8], bb[8];
            *(float4*)&a[0]  = *(const float4*)&As[kk][tr * 8];
            *(float4*)&a[4]  = *(const float4*)&As[kk][tr * 8 + 4];
            *(float4*)&bb[0] = *(const float4*)&Bs[kk][tc * 8];
            *(float4*)&bb[4] = *(const float4*)&Bs[kk][tc * 8 + 4];
#pragma unroll
            for (int i = 0; i < 8; i++)
#pragma unroll
                for (int j = 0; j < 8; j++) acc[i][j] += a[i] * bb[j];
        }
    };

    // prologue: tile 0 -> smem
    {
        float4 av = loadA(0);
        float4 wv = loadW(0);
        commit(av, wv);
    }
    __syncthreads();

    // pipelined mainloop: prefetch k0 while computing k0-BK
    for (int k0 = BK; k0 < K; k0 += BK) {
        float4 av = loadA(k0);     // LDGs issue here...
        float4 wv = loadW(k0);
        computeTile();             // ...and drain behind 512 FMAs
        __syncthreads();
        commit(av, wv);
        __syncthreads();
    }
    computeTile();                 // epilogue tile

#pragma unroll
    for (int i = 0; i < 8; i++) {
        int m = m0 + tr * 8 + i;
        if (m >= M) continue;
        size_t rowoff = (size_t)m * ldc;
#pragma unroll
        for (int jj = 0; jj < 2; jj++) {
            int n = n0 + tc * 8 + jj * 4;
            if (n < Nout) {
                float4 cv;
                cv.x = acc[i][jj * 4 + 0]; cv.y = acc[i][jj * 4 + 1];
                cv.z = acc[i][jj * 4 + 2]; cv.w = acc[i][jj * 4 + 3];
                if (bias) {
                    cv.x += bias[n + 0]; cv.y += bias[n + 1];
                    cv.z += bias[n + 2]; cv.w += bias[n + 3];
                }
                if (relu) {
                    cv.x = fmaxf(cv.x, 0.f); cv.y = fmaxf(cv.y, 0.f);
                    cv.z = fmaxf(cv.z, 0.f); cv.w = fmaxf(cv.w, 0.f);
                }
                *(float4*)&C[rowoff + n] = cv;
            }
        }
    }
}

// ---------------- fused attention (one block per batch row) ----------------
__global__ __launch_bounds__(256) void attn_kernel(
    const float* __restrict__ seq, const float* __restrict__ seq_e,
    const float* __restrict__ seq_ts, const void* __restrict__ mask,
    const float* __restrict__ freq, const float* __restrict__ phase,
    float* __restrict__ attn_out, int Brt)
{
    const int b = blockIdx.x;
    const int tid = threadIdx.x;
    const int warp = tid >> 5, lane = tid & 31;

    __shared__ float sK[N_][DM_];      // k_in = [seq | seq_e | seq_t]
    __shared__ float sP[H_ * DM_];     // p[b]
    __shared__ float slog[H_][N_];
    __shared__ float sattn[H_][N_];

    const float4* s4  = (const float4*)(seq   + (size_t)b * N_ * D_);
    const float4* se4 = (const float4*)(seq_e + (size_t)b * N_ * D_);
    for (int i = tid; i < N_ * D_ / 4; i += 256) {
        int n = i >> 5, d4 = (i & 31) << 2;
        float4 v = s4[i];  *(float4*)&sK[n][d4]       = v;
        float4 w = se4[i]; *(float4*)&sK[n][128 + d4] = w;
    }
    for (int i = tid; i < N_ * D_; i += 256) {
        int n = i >> 7, d = i & 127;
        sK[n][256 + d] = cosf(seq_ts[(size_t)b * N_ + n] * freq[d] + phase[d]);
    }
    const float4* p4 = (const float4*)(g_p + (size_t)b * (H_ * DM_));
    for (int i = tid; i < H_ * DM_ / 4; i += 256)
        ((float4*)sP)[i] = p4[i];
    __syncthreads();

    const float scale = 0.102062072615965696f;  // 1/sqrt(96)
    for (int pr = warp; pr < H_ * N_; pr += 8) {
        int h = pr / N_, n = pr % N_;
        const float* pp = &sP[h * DM_];
        float s = 0.0f;
        for (int j = lane; j < DM_; j += 32) s += pp[j] * sK[n][j];
#pragma unroll
        for (int o = 16; o; o >>= 1) s += __shfl_xor_sync(0xffffffffu, s, o);
        if (lane == 0) slog[h][n] = s * scale;
    }
    __syncthreads();

    if (warp < H_) {
        int mode = g_maskmode;
        float lg = -3.0e38f;
        if (lane < N_) {
            lg = slog[warp][lane];
            if (mask_at(mask, mode, (size_t)b * N_ + lane)) lg = -1.0e10f;
        }
        float mx = lg;
#pragma unroll
        for (int o = 16; o; o >>= 1) mx = fmaxf(mx, __shfl_xor_sync(0xffffffffu, mx, o));
        float e = (lane < N_) ? expf(lg - mx) : 0.0f;
        float sm = e;
#pragma unroll
        for (int o = 16; o; o >>= 1) sm += __shfl_xor_sync(0xffffffffu, sm, o);
        float a = e / sm;
        if (lane < N_) {
            sattn[warp][lane] = a;
            attn_out[((size_t)warp * Brt + b) * N_ + lane] = a;  // attn_sq[h*B+b, n]
        }
    }
    __syncthreads();

    for (int j = tid; j < H_ * DM_; j += 256) {
        int h = j / DM_, jj = j - h * DM_;
        float s = 0.0f;
#pragma unroll
        for (int n = 0; n < N_; n++) s += sattn[h][n] * sK[n][jj];
        g_u[(size_t)b * (H_ * DM_) + j] = s;
    }
}

// ---------------- residual + LayerNorm + build MLP input -------------------
// Residual uses compact g_qin2: q_in = [qin2[0:128] | 0 | qin2[128:256]].
__global__ __launch_bounds__(128) void ln_kernel(
    const float* __restrict__ src,
    const float* __restrict__ ln_g, const float* __restrict__ ln_b)
{
    const int b = blockIdx.x, tid = threadIdx.x;
    const int warp = tid >> 5, lane = tid & 31;
    __shared__ float ws[8];

    const float* fcrow = &g_fc[(size_t)b * DM_];
    const float* q2row = &g_qin2[(size_t)b * 256];

    float v[3];
    v[0] = fcrow[tid]       + q2row[tid];
    v[1] = fcrow[tid + 128];
    v[2] = fcrow[tid + 256] + q2row[tid + 128];
    float s = v[0] + v[1] + v[2];
#pragma unroll
    for (int o = 16; o; o >>= 1) s += __shfl_xor_sync(0xffffffffu, s, o);
    if (lane == 0) ws[warp] = s;
    __syncthreads();
    float mu = (ws[0] + ws[1] + ws[2] + ws[3]) * (1.0f / 384.0f);

    float d2 = 0.0f;
#pragma unroll
    for (int i = 0; i < 3; i++) { float d = v[i] - mu; d2 += d * d; }
#pragma unroll
    for (int o = 16; o; o >>= 1) d2 += __shfl_xor_sync(0xffffffffu, d2, o);
    if (lane == 0) ws[4 + warp] = d2;
    __syncthreads();
    float var = (ws[4] + ws[5] + ws[6] + ws[7]) * (1.0f / 384.0f);
    float rs = rsqrtf(var + 1e-5f);

#pragma unroll
    for (int i = 0; i < 3; i++) {
        int j = tid + i * 128;
        g_x[(size_t)b * 512 + j] = (v[i] - mu) * rs * ln_g[j] + ln_b[j];
    }
    g_x[(size_t)b * 512 + 384 + tid] = src[(size_t)b * D_ + tid];
}

// ---------------- host launcher -------------------------------------------
extern "C" void kernel_launch(void* const* d_in, const int* in_sizes, int n_in,
                              void* d_out, int out_size)
{
    const float* src    = (const float*)d_in[0];
    const float* seq    = (const float*)d_in[1];
    const float* seq_e  = (const float*)d_in[2];
    const float* src_ts = (const float*)d_in[3];
    const float* seq_ts = (const float*)d_in[4];
    const void*  mask   = d_in[5];
    const float* freq   = (const float*)d_in[6];
    const float* phase  = (const float*)d_in[7];
    const float* Wq     = (const float*)d_in[8];
    const float* Wk     = (const float*)d_in[9];
    const float* Wv     = (const float*)d_in[10];
    const float* fc_w   = (const float*)d_in[11];
    const float* fc_b   = (const float*)d_in[12];
    const float* ln_g   = (const float*)d_in[13];
    const float* ln_b   = (const float*)d_in[14];
    const float* m1_w   = (const float*)d_in[15];
    const float* m1_b   = (const float*)d_in[16];
    const float* m2_w   = (const float*)d_in[17];
    const float* m2_b   = (const float*)d_in[18];

    // runtime batch (defensive: derive from src element count, cap at B_)
    int Brt = in_sizes[0] / D_;
    if (Brt <= 0 || Brt > B_) Brt = B_;
    int mblocks = (Brt + BM - 1) / BM;

    float* y        = (float*)d_out;                    // (B,128)
    float* attn_out = y + (size_t)Brt * D_;             // (H*B, N)

    float *p_qin2, *p_q, *p_p, *p_u, *p_o0, *p_fc, *p_x, *p_hh;
    cudaGetSymbolAddress((void**)&p_qin2, g_qin2);
    cudaGetSymbolAddress((void**)&p_q,    g_q);
    cudaGetSymbolAddress((void**)&p_p,    g_p);
    cudaGetSymbolAddress((void**)&p_u,    g_u);
    cudaGetSymbolAddress((void**)&p_o0,   g_o0);
    cudaGetSymbolAddress((void**)&p_fc,   g_fc);
    cudaGetSymbolAddress((void**)&p_x,    g_x);
    cudaGetSymbolAddress((void**)&p_hh,   g_hh);

    int mwords = (Brt * N_) / 4;               // bytes/4 lower bound for any dtype >= u8
    detect_mask_kernel<<<1, 256>>>((const unsigned int*)mask, mwords > 0 ? mwords : 1);
    timeq_kernel<<<Brt, 128>>>(src, src_ts, freq, phase);

    dim3 blk(256);
    // q = [src|src_t] @ Wq(cols 0..127,256..383)^T  (M=B, K=256, N=384)
    sgemm_kernel<true ><<<dim3(3, mblocks, 1), blk>>>(p_qin2, 256, 0, Wq, 384, 0,
                                                      p_q, 384, 0, Brt, 384, 256, nullptr, 0, 128);
    // p[:,h,:] = q_h @ Wk_h (M=B, K=96, N=384) x4 heads
    sgemm_kernel<false><<<dim3(3, mblocks, 4), blk>>>(p_q, 384, 96, Wk, 384, 96 * 384,
                                                      p_p, 1536, 384, Brt, 384, 96, nullptr, 0, 0);
    // attention: logits, softmax (-> attn_sq output), u = attn @ k_in
    attn_kernel<<<Brt, 256>>>(seq, seq_e, seq_ts, mask, freq, phase, attn_out, Brt);
    // out0[:,h,:] = u_h @ Wv_h^T (M=B, K=384, N=96) x4 heads
    sgemm_kernel<true ><<<dim3(1, mblocks, 4), blk>>>(p_u, 1536, 384, Wv, 384, 96 * 384,
                                                      p_o0, 384, 96, Brt, 96, 384, nullptr, 0, 0);
    // fc = out0 @ fc_w^T + fc_b (M=B, K=384, N=384)
    sgemm_kernel<true ><<<dim3(3, mblocks, 1), blk>>>(p_o0, 384, 0, fc_w, 384, 0,
                                                      p_fc, 384, 0, Brt, 384, 384, fc_b, 0, 0);
    // residual + LN, build x = [LN | src]
    ln_kernel<<<Brt, 128>>>(src, ln_g, ln_b);
    // h = relu(x @ m1_w^T + m1_b) (M=B, K=512, N=128)
    sgemm_kernel<true ><<<dim3(1, mblocks, 1), blk>>>(p_x, 512, 0, m1_w, 512, 0,
                                                      p_hh, 128, 0, Brt, 128, 512, m1_b, 1, 0);
    // y = h @ m2_w^T + m2_b (M=B, K=128, N=128)
    sgemm_kernel<true ><<<dim3(1, mblocks, 1), blk>>>(p_hh, 128, 0, m2_w, 128, 0,
                                                      y, 128, 0, Brt, 128, 128, m2_b, 0, 0);
}